// round 1
// baseline (speedup 1.0000x reference)
#include <cuda_runtime.h>
#include <cuda_bf16.h>

// Problem constants
#define BB 256
#define TT 512
#define FF 128
#define HH 256
#define NQ 4

// Accurate-enough fast transcendentals (EX2/RCP MUFU based, ~1e-7 rel err)
__device__ __forceinline__ float fast_sig(float x) {
    float e = __expf(-x);
    return __fdividef(1.0f, 1.0f + e);
}
__device__ __forceinline__ float fast_tanh(float x) {
    x = fminf(fmaxf(x, -15.0f), 15.0f);   // guard exp overflow -> NaN
    float e = __expf(2.0f * x);
    return __fdividef(e - 1.0f, e + 1.0f);
}

__global__ __launch_bounds__(256, 2)
void qlstm_kernel(const float* __restrict__ x,      // [B, T, F]
                  const float* __restrict__ W_in,   // [H+F, NQ]
                  const float* __restrict__ b_in,   // [NQ]
                  const float* __restrict__ Wq,     // [4, NQ, NQ]
                  const float* __restrict__ bq,     // [4, NQ]
                  const float* __restrict__ W_out,  // [NQ, H]
                  const float* __restrict__ b_out,  // [H]
                  float* __restrict__ out)          // [B*T*H] + [B*H] + [B*H]
{
    __shared__ float4 sxp[TT];        // precomputed x-projection + b_in, per t
    __shared__ float4 sWx[FF];        // W_in rows H..H+F-1 (each row = 4 floats)
    __shared__ float4 spart[8];       // per-warp partial y
    __shared__ float4 sq4[4];         // q[k][r] as 4 float4 (k-major)
    __shared__ float  sWq[64];
    __shared__ float  sbq[16];

    const int tid  = threadIdx.x;
    const int lane = tid & 31;
    const int warp = tid >> 5;
    const int b    = blockIdx.x;

    // ---- stage small weights into SMEM ----
    if (tid < FF) sWx[tid] = *reinterpret_cast<const float4*>(W_in + (size_t)(HH + tid) * NQ);
    if (tid < 64) sWq[tid] = Wq[tid];
    if (tid < 16) sbq[tid] = bq[tid];
    const float4 b4 = *reinterpret_cast<const float4*>(b_in);
    __syncthreads();

    // ---- prologue: xp[t] = x[b,t,:] @ W_in[H:,:] + b_in  (recurrence-free) ----
    for (int t = tid; t < TT; t += 256) {
        const float4* xr = reinterpret_cast<const float4*>(x + ((size_t)b * TT + t) * FF);
        float4 acc = b4;
        #pragma unroll
        for (int f4 = 0; f4 < FF / 4; f4++) {
            float4 xv = xr[f4];
            float4 w0 = sWx[4 * f4 + 0];
            float4 w1 = sWx[4 * f4 + 1];
            float4 w2 = sWx[4 * f4 + 2];
            float4 w3 = sWx[4 * f4 + 3];
            acc.x = fmaf(xv.x, w0.x, fmaf(xv.y, w1.x, fmaf(xv.z, w2.x, fmaf(xv.w, w3.x, acc.x))));
            acc.y = fmaf(xv.x, w0.y, fmaf(xv.y, w1.y, fmaf(xv.z, w2.y, fmaf(xv.w, w3.y, acc.y))));
            acc.z = fmaf(xv.x, w0.z, fmaf(xv.y, w1.z, fmaf(xv.z, w2.z, fmaf(xv.w, w3.z, acc.z))));
            acc.w = fmaf(xv.x, w0.w, fmaf(xv.y, w1.w, fmaf(xv.z, w2.w, fmaf(xv.w, w3.w, acc.w))));
        }
        sxp[t] = acc;
    }

    // ---- per-thread persistent state & weights ----
    const float4 wh = *reinterpret_cast<const float4*>(W_in + (size_t)tid * NQ); // h-part row
    const float wo0 = W_out[0 * HH + tid];
    const float wo1 = W_out[1 * HH + tid];
    const float wo2 = W_out[2 * HH + tid];
    const float wo3 = W_out[3 * HH + tid];
    const float bo  = b_out[tid];

    float h = 0.0f, c = 0.0f;
    float* hs = out + ((size_t)b * TT) * HH + tid;

    __syncthreads();  // sxp ready

    for (int t = 0; t < TT; t++) {
        // ---- phase A: y partials, warp butterfly reduce ----
        float4 p;
        p.x = h * wh.x; p.y = h * wh.y; p.z = h * wh.z; p.w = h * wh.w;
        #pragma unroll
        for (int off = 16; off; off >>= 1) {
            p.x += __shfl_xor_sync(0xffffffffu, p.x, off);
            p.y += __shfl_xor_sync(0xffffffffu, p.y, off);
            p.z += __shfl_xor_sync(0xffffffffu, p.z, off);
            p.w += __shfl_xor_sync(0xffffffffu, p.w, off);
        }
        if (lane == 0) spart[warp] = p;
        __syncthreads();

        // ---- phase B: 16 lanes of warp 0 compute q[k][r] ----
        if (tid < 16) {
            float4 s0 = spart[0], s1 = spart[1], s2 = spart[2], s3 = spart[3];
            float4 s4 = spart[4], s5 = spart[5], s6 = spart[6], s7 = spart[7];
            float4 xv = sxp[t];
            float y0 = xv.x + s0.x + s1.x + s2.x + s3.x + s4.x + s5.x + s6.x + s7.x;
            float y1 = xv.y + s0.y + s1.y + s2.y + s3.y + s4.y + s5.y + s6.y + s7.y;
            float y2 = xv.z + s0.z + s1.z + s2.z + s3.z + s4.z + s5.z + s6.z + s7.z;
            float y3 = xv.w + s0.w + s1.w + s2.w + s3.w + s4.w + s5.w + s6.w + s7.w;
            int base = ((tid >> 2) << 4) + (tid & 3);   // k*16 + r
            float acc = sbq[tid];
            acc = fmaf(y0, sWq[base +  0], acc);
            acc = fmaf(y1, sWq[base +  4], acc);
            acc = fmaf(y2, sWq[base +  8], acc);
            acc = fmaf(y3, sWq[base + 12], acc);
            reinterpret_cast<float*>(sq4)[tid] = fast_tanh(acc);
        }
        __syncthreads();

        // ---- phase C: every thread computes its gate quad & updates state ----
        float4 q0 = sq4[0], q1 = sq4[1], q2 = sq4[2], q3 = sq4[3];
        float z0 = fmaf(q0.x, wo0, fmaf(q0.y, wo1, fmaf(q0.z, wo2, fmaf(q0.w, wo3, bo))));
        float z1 = fmaf(q1.x, wo0, fmaf(q1.y, wo1, fmaf(q1.z, wo2, fmaf(q1.w, wo3, bo))));
        float z2 = fmaf(q2.x, wo0, fmaf(q2.y, wo1, fmaf(q2.z, wo2, fmaf(q2.w, wo3, bo))));
        float z3 = fmaf(q3.x, wo0, fmaf(q3.y, wo1, fmaf(q3.z, wo2, fmaf(q3.w, wo3, bo))));
        float ig = fast_sig(z0);
        float fg = fast_sig(z1);
        float gg = fast_tanh(z2);
        float og = fast_sig(z3);
        c = fmaf(fg, c, ig * gg);
        h = og * fast_tanh(c);
        hs[(size_t)t * HH] = h;
    }

    // ---- final states ----
    const size_t seq_elems = (size_t)BB * TT * HH;
    out[seq_elems + (size_t)b * HH + tid] = h;
    out[seq_elems + (size_t)BB * HH + (size_t)b * HH + tid] = c;
}

extern "C" void kernel_launch(void* const* d_in, const int* in_sizes, int n_in,
                              void* d_out, int out_size) {
    const float* x     = (const float*)d_in[0];
    const float* W_in  = (const float*)d_in[1];
    const float* b_in  = (const float*)d_in[2];
    const float* Wq    = (const float*)d_in[3];
    const float* bq    = (const float*)d_in[4];
    const float* W_out = (const float*)d_in[5];
    const float* b_out = (const float*)d_in[6];
    float* out = (float*)d_out;
    qlstm_kernel<<<BB, 256>>>(x, W_in, b_in, Wq, bq, W_out, b_out, out);
}